// round 4
// baseline (speedup 1.0000x reference)
#include <cuda_runtime.h>

#define BATCH 256
#define TT    2048
#define FEAT  10
#define HID   64
#define GATES 192   // 3*HID

typedef unsigned long long ull;

__device__ __forceinline__ ull ffma2(ull a, ull b, ull c) {
    ull d;
    asm("fma.rn.f32x2 %0, %1, %2, %3;" : "=l"(d) : "l"(a), "l"(b), "l"(c));
    return d;
}
__device__ __forceinline__ ull pack2(float lo, float hi) {
    ull r;
    asm("mov.b64 %0, {%1, %2};" : "=l"(r) : "f"(lo), "f"(hi));
    return r;
}
__device__ __forceinline__ float2 unpack2(ull a) {
    float lo, hi;
    asm("mov.b64 {%0, %1}, %2;" : "=f"(lo), "=f"(hi) : "l"(a));
    return make_float2(lo, hi);
}

// sigmoid via hardware EX2/RCP (~1e-7 rel err, plenty under 1e-3 tolerance)
__device__ __forceinline__ float sigmoid_f(float x) {
    return __fdividef(1.0f, 1.0f + __expf(-x));
}
// tanh(x) = 1 - 2/(1+exp(2x)); saturates correctly for |x| large (inf/0 paths)
__device__ __forceinline__ float tanh_f(float x) {
    return 1.0f - 2.0f * __fdividef(1.0f, 1.0f + __expf(2.0f * x));
}

extern "C" __global__ void __launch_bounds__(GATES, 2)
gru_kernel(const float* __restrict__ noise,
           const float* __restrict__ w_ih,
           const float* __restrict__ w_hh,
           const float* __restrict__ b_ih,
           const float* __restrict__ b_hh,
           float* __restrict__ out)
{
    extern __shared__ float smem[];
    float* s_noise = smem;                   // TT*FEAT = 20480 floats (80 KB)
    float* s_h     = smem + TT * FEAT;       // 64 floats (16B-aligned: 81920 B offset)
    float* s_pre   = s_h + HID;              // 192 floats
    float* s_dn    = s_pre + GATES;          // 64 floats

    const int o = threadIdx.x;               // gate-output row 0..191
    const int b = blockIdx.x;                // batch element

    // ---- Preload this batch element's entire noise stream into shared ----
    {
        const float4* g4 = (const float4*)(noise + (size_t)b * TT * FEAT);
        float4* s4 = (float4*)s_noise;
        #pragma unroll 4
        for (int i = o; i < (TT * FEAT) / 4; i += GATES) s4[i] = g4[i];
    }
    if (o < HID) s_h[o] = 0.0f;

    // ---- Recurrent weights for row o: 64 floats packed into 32 b64 regs ----
    ull wp[32];
    {
        const float4* w4 = (const float4*)(w_hh + o * HID);
        #pragma unroll
        for (int i = 0; i < 16; i++) {
            float4 w = w4[i];
            wp[2 * i]     = pack2(w.x, w.y);
            wp[2 * i + 1] = pack2(w.z, w.w);
        }
    }
    // Input-projection weights for row o
    float wi[FEAT];
    #pragma unroll
    for (int i = 0; i < FEAT; i++) wi[i] = w_ih[o * FEAT + i];

    const float bi = b_ih[o];
    const float bh = b_hh[o];
    // r/z rows: fold b_ih + b_hh into one bias. n row: b_hh must stay inside
    // the r*(...) term, keep it separate.
    const float gi_bias = (o < 2 * HID) ? (bi + bh) : bi;

    __syncthreads();

    // input projection for t=0
    float gi = gi_bias;
    {
        const float* np = s_noise;
        #pragma unroll
        for (int i = 0; i < FEAT; i++) gi = fmaf(np[i], wi[i], gi);
    }

    float* outb = out + (size_t)b * TT * HID;

    for (int t = 0; t < TT; t++) {
        // ---- recurrent matvec row: dot(h, w_hh[o,:]) via packed f32x2 FMA ----
        ull a0 = 0ull, a1 = 0ull, a2 = 0ull, a3 = 0ull;
        const ulonglong2* h2 = (const ulonglong2*)s_h;
        #pragma unroll
        for (int i = 0; i < 16; i += 2) {
            ulonglong2 hv0 = h2[i];       // LDS.128 broadcast (4 h values)
            ulonglong2 hv1 = h2[i + 1];
            a0 = ffma2(wp[2 * i],     hv0.x, a0);
            a1 = ffma2(wp[2 * i + 1], hv0.y, a1);
            a2 = ffma2(wp[2 * i + 2], hv1.x, a2);
            a3 = ffma2(wp[2 * i + 3], hv1.y, a3);
        }
        float2 f0 = unpack2(a0), f1 = unpack2(a1);
        float2 f2 = unpack2(a2), f3 = unpack2(a3);
        float dot = ((f0.x + f0.y) + (f1.x + f1.y)) +
                    ((f2.x + f2.y) + (f3.x + f3.y));

        if (o < 2 * HID) {
            s_pre[o] = gi + dot;              // full pre-activation for r/z
        } else {
            s_pre[o] = gi;                    // g_n (with b_ih_n)
            s_dn[o - 2 * HID] = dot + bh;     // h@w_hn^T + b_hn
        }
        __syncthreads();

        // Overlap: compute next step's input projection (independent of h)
        if (t + 1 < TT) {
            const float* np = s_noise + (t + 1) * FEAT;
            float g = gi_bias;
            #pragma unroll
            for (int i = 0; i < FEAT; i++) g = fmaf(np[i], wi[i], g);
            gi = g;
        }

        // ---- epilogue: 64 threads combine gates ----
        if (o < HID) {
            float r = sigmoid_f(s_pre[o]);
            float z = sigmoid_f(s_pre[HID + o]);
            float n = tanh_f(fmaf(r, s_dn[o], s_pre[2 * HID + o]));
            float h = fmaf(z, s_h[o] - n, n);   // (1-z)*n + z*h_old
            s_h[o] = h;
            outb[(size_t)t * HID + o] = h;
        }
        __syncthreads();
    }
}

extern "C" void kernel_launch(void* const* d_in, const int* in_sizes, int n_in,
                              void* d_out, int out_size)
{
    const float* noise = (const float*)d_in[0];
    const float* w_ih  = (const float*)d_in[1];
    const float* w_hh  = (const float*)d_in[2];
    const float* b_ih  = (const float*)d_in[3];
    const float* b_hh  = (const float*)d_in[4];
    float* out = (float*)d_out;

    const size_t smem_bytes =
        (size_t)(TT * FEAT + HID + GATES + HID) * sizeof(float);  // 83200 B

    cudaFuncSetAttribute(gru_kernel,
                         cudaFuncAttributeMaxDynamicSharedMemorySize,
                         (int)smem_bytes);

    gru_kernel<<<BATCH, GATES, smem_bytes>>>(noise, w_ih, w_hh, b_ih, b_hh, out);
}